// round 1
// baseline (speedup 1.0000x reference)
#include <cuda_runtime.h>
#include <cuda_bf16.h>

// Problem shape (fixed for this dataset entry)
#define BB_ 64
#define SS_ 512
#define HH_ 1024
#define LL_ 9

#define ROWS_PER_WARP 4
#define WARPS_PER_BLOCK 8
#define TPB 256
#define ROWS_PER_BLOCK (ROWS_PER_WARP * WARPS_PER_BLOCK)  // 32

// Scratch (no device mallocs allowed)
__device__ int g_src[BB_ * SS_];
__device__ int g_nvalid[BB_];

// ---------------------------------------------------------------------------
// Kernel 1: per-batch stable compaction map via prefix sum over the mask.
// g_src[b*S + d] = source token index of the d-th valid token in batch b.
// ---------------------------------------------------------------------------
__global__ void compact_kernel(const int* __restrict__ mask) {
    int b = blockIdx.x;
    int s = threadIdx.x;                 // 0..511
    int lane = s & 31, wid = s >> 5;     // 16 warps
    int m = (mask[b * SS_ + s] != 0) ? 1 : 0;

    unsigned bal = __ballot_sync(0xffffffffu, m);
    int lanePrefix = __popc(bal & ((1u << lane) - 1u));

    __shared__ int wsum[16];
    if (lane == 0) wsum[wid] = __popc(bal);
    __syncthreads();

    if (s < 16) {
        int v = wsum[s];
        #pragma unroll
        for (int off = 1; off < 16; off <<= 1) {
            int u = __shfl_up_sync(0x0000ffffu, v, off);
            if (s >= off) v += u;
        }
        wsum[s] = v;  // inclusive scan of warp totals
    }
    __syncthreads();

    int base = (wid == 0) ? 0 : wsum[wid - 1];
    if (m) g_src[b * SS_ + base + lanePrefix] = s;
    if (s == 0) g_nvalid[b] = wsum[15];
}

// ---------------------------------------------------------------------------
// Kernel 2: per-warp 4-row fused GEMV(H->9) + bias + softmax.
// W staged in smem transposed as Wt[j][k] (float4), broadcast-read per warp;
// x rows loaded as coalesced float4; 36 fp32 accumulators; butterfly reduce.
// Invalid rows (d >= n_valid) cost nothing: softmax(bias) written directly.
// ---------------------------------------------------------------------------
__global__ __launch_bounds__(TPB, 2)
void bertner_main_kernel(const float* __restrict__ seq,
                         const float* __restrict__ W,
                         const float* __restrict__ bias,
                         float* __restrict__ out) {
    __shared__ float4 sWt4[LL_ * (HH_ / 4)];  // 9 * 256 float4 = 36 KB
    __shared__ float sb[LL_];

    int tid  = threadIdx.x;
    int lane = tid & 31;
    int warp = tid >> 5;

    int rowBlock = blockIdx.x * ROWS_PER_BLOCK;        // 32 rows, single batch
    int bb = rowBlock >> 9;                            // / 512
    int nv = g_nvalid[bb];
    bool blockHasValid = (rowBlock & 511) < nv;

    if (tid < LL_) sb[tid] = bias[tid];
    if (blockHasValid) {
        float* sWt = (float*)sWt4;
        // Coalesced read of W [H,L], transposed scatter into smem Wt [L,H]
        for (int idx = tid; idx < HH_ * LL_; idx += TPB) {
            float v = W[idx];
            int k = idx / LL_;
            int j = idx - k * LL_;
            sWt[j * HH_ + k] = v;
        }
    }
    __syncthreads();

    int row0 = rowBlock + warp * ROWS_PER_WARP;

    const float4* xp[ROWS_PER_WARP];
    bool valid[ROWS_PER_WARP];
    int nValidHere = 0;
    #pragma unroll
    for (int p = 0; p < ROWS_PER_WARP; p++) {
        int r = row0 + p;
        int d = r & 511;
        valid[p] = (d < nv);
        int srcTok = valid[p] ? g_src[r] : 0;
        xp[p] = (const float4*)(seq + ((size_t)bb * SS_ + (size_t)srcTok) * HH_);
        nValidHere += valid[p] ? 1 : 0;
    }

    float acc[ROWS_PER_WARP][LL_];
    #pragma unroll
    for (int p = 0; p < ROWS_PER_WARP; p++)
        #pragma unroll
        for (int j = 0; j < LL_; j++) acc[p][j] = 0.0f;

    if (nValidHere > 0) {
        #pragma unroll
        for (int i = 0; i < HH_ / 4 / 32; i++) {   // 8 iterations
            int kk = i * 32 + lane;                // float4 index along H
            float4 w[LL_];
            #pragma unroll
            for (int j = 0; j < LL_; j++) w[j] = sWt4[j * 256 + kk];
            #pragma unroll
            for (int p = 0; p < ROWS_PER_WARP; p++) {
                if (valid[p]) {
                    float4 xv = xp[p][kk];
                    #pragma unroll
                    for (int j = 0; j < LL_; j++) {
                        acc[p][j] = fmaf(xv.x, w[j].x, acc[p][j]);
                        acc[p][j] = fmaf(xv.y, w[j].y, acc[p][j]);
                        acc[p][j] = fmaf(xv.z, w[j].z, acc[p][j]);
                        acc[p][j] = fmaf(xv.w, w[j].w, acc[p][j]);
                    }
                }
            }
        }
        // Butterfly reduce each of the 36 partials across the warp
        #pragma unroll
        for (int p = 0; p < ROWS_PER_WARP; p++)
            #pragma unroll
            for (int j = 0; j < LL_; j++) {
                float v = acc[p][j];
                #pragma unroll
                for (int off = 16; off >= 1; off >>= 1)
                    v += __shfl_xor_sync(0xffffffffu, v, off);
                acc[p][j] = v;
            }
    }

    // Epilogue: lane p handles row p (static register indexing via unroll+guard)
    #pragma unroll
    for (int p = 0; p < ROWS_PER_WARP; p++) {
        if (lane == p) {
            int r = row0 + p;
            float l[LL_];
            float mx = -3.402823466e+38f;
            #pragma unroll
            for (int j = 0; j < LL_; j++) {
                l[j] = acc[p][j] + sb[j];
                mx = fmaxf(mx, l[j]);
            }
            float ssum = 0.0f;
            #pragma unroll
            for (int j = 0; j < LL_; j++) {
                l[j] = __expf(l[j] - mx);
                ssum += l[j];
            }
            float inv = __fdividef(1.0f, ssum);
            float* o = out + (size_t)r * LL_;
            #pragma unroll
            for (int j = 0; j < LL_; j++) o[j] = l[j] * inv;
        }
    }
}

// ---------------------------------------------------------------------------
extern "C" void kernel_launch(void* const* d_in, const int* in_sizes, int n_in,
                              void* d_out, int out_size) {
    const float* seq  = (const float*)d_in[0];   // [B,S,H] f32
    const int*   mask = (const int*)d_in[1];     // [B,S]   i32
    const float* W    = (const float*)d_in[2];   // [H,L]   f32
    const float* bias = (const float*)d_in[3];   // [L]     f32
    float* out = (float*)d_out;                  // [B,S,L] f32

    compact_kernel<<<BB_, SS_>>>(mask);

    int grid = (BB_ * SS_) / ROWS_PER_BLOCK;     // 1024
    bertner_main_kernel<<<grid, TPB>>>(seq, W, bias, out);
}

// round 2
// speedup vs baseline: 1.0151x; 1.0151x over previous
#include <cuda_runtime.h>
#include <cuda_bf16.h>

// Problem shape (fixed)
#define BB_ 64
#define SS_ 512
#define HH_ 1024
#define LL_ 9

#define ROWS_PER_WARP 2
#define WARPS_PER_BLOCK 8
#define TPB 256
#define ROWS_PER_BLOCK (ROWS_PER_WARP * WARPS_PER_BLOCK)  // 16

__device__ int g_src[BB_ * SS_];
__device__ int g_nvalid[BB_];

typedef unsigned long long u64;

__device__ __forceinline__ u64 fma2(u64 a, u64 b, u64 c) {
    u64 d;
    asm("fma.rn.f32x2 %0, %1, %2, %3;" : "=l"(d) : "l"(a), "l"(b), "l"(c));
    return d;
}
__device__ __forceinline__ u64 add2(u64 a, u64 b) {
    u64 d;
    asm("add.rn.f32x2 %0, %1, %2;" : "=l"(d) : "l"(a), "l"(b));
    return d;
}
__device__ __forceinline__ float pair_sum(u64 v) {
    float lo = __uint_as_float((unsigned)(v & 0xffffffffull));
    float hi = __uint_as_float((unsigned)(v >> 32));
    return lo + hi;
}

// ---------------------------------------------------------------------------
// Kernel 1: per-batch stable compaction map (prefix sum over mask).
// ---------------------------------------------------------------------------
__global__ void compact_kernel(const int* __restrict__ mask) {
    int b = blockIdx.x;
    int s = threadIdx.x;                 // 0..511
    int lane = s & 31, wid = s >> 5;     // 16 warps
    int m = (mask[b * SS_ + s] != 0) ? 1 : 0;

    unsigned bal = __ballot_sync(0xffffffffu, m);
    int lanePrefix = __popc(bal & ((1u << lane) - 1u));

    __shared__ int wsum[16];
    if (lane == 0) wsum[wid] = __popc(bal);
    __syncthreads();

    if (s < 16) {
        int v = wsum[s];
        #pragma unroll
        for (int off = 1; off < 16; off <<= 1) {
            int u = __shfl_up_sync(0x0000ffffu, v, off);
            if (s >= off) v += u;
        }
        wsum[s] = v;
    }
    __syncthreads();

    int base = (wid == 0) ? 0 : wsum[wid - 1];
    if (m) g_src[b * SS_ + base + lanePrefix] = s;
    if (s == 0) g_nvalid[b] = wsum[15];
}

// ---------------------------------------------------------------------------
// Kernel 2: warp computes 2 rows. GEMV via f32x2 packed FMA (pairs along k).
// W transposed in smem: Wt[j][k], read as ulonglong2 (two f32 pairs) per lane.
// Invalid rows cost nothing (acc=0 -> softmax(bias)).
// ---------------------------------------------------------------------------
__global__ __launch_bounds__(TPB, 4)
void bertner_main_kernel(const float* __restrict__ seq,
                         const float* __restrict__ W,
                         const float* __restrict__ bias,
                         float* __restrict__ out) {
    __shared__ ulonglong2 sW2[LL_ * 256];   // [j][k4] : 9*256*16B = 36 KB
    __shared__ float sb[LL_];

    int tid  = threadIdx.x;
    int lane = tid & 31;
    int warp = tid >> 5;

    int rowBlock = blockIdx.x * ROWS_PER_BLOCK;   // 16 rows, single batch
    int bb = rowBlock >> 9;
    int nv = g_nvalid[bb];
    bool blockHasValid = (rowBlock & 511) < nv;

    if (tid < LL_) sb[tid] = bias[tid];
    if (blockHasValid) {
        float* sWtF = (float*)sW2;
        // Coalesced read of W [H,L]; transposed scatter -> Wt [L,H]
        for (int idx = tid; idx < HH_ * LL_; idx += TPB) {
            float v = W[idx];
            int k = idx / LL_;
            int j = idx - k * LL_;
            sWtF[j * HH_ + k] = v;
        }
    }
    __syncthreads();

    int row0 = rowBlock + warp * ROWS_PER_WARP;
    int d0 = row0 & 511;
    bool v0 = d0 < nv;
    bool v1 = (d0 + 1) < nv;

    int src0 = v0 ? g_src[row0] : 0;
    int src1 = v1 ? g_src[row0 + 1] : 0;
    const ulonglong2* x0 = (const ulonglong2*)(seq + ((size_t)bb * SS_ + (size_t)src0) * HH_);
    const ulonglong2* x1 = (const ulonglong2*)(seq + ((size_t)bb * SS_ + (size_t)src1) * HH_);

    u64 acc0[LL_], acc1[LL_];
    #pragma unroll
    for (int j = 0; j < LL_; j++) { acc0[j] = 0ull; acc1[j] = 0ull; }

    if (v0 || v1) {
        #pragma unroll 2
        for (int i = 0; i < HH_ / 4 / 32; i++) {   // 8 iterations
            int k4 = i * 32 + lane;                // float4 index along H
            ulonglong2 xv0 = make_ulonglong2(0ull, 0ull);
            ulonglong2 xv1 = make_ulonglong2(0ull, 0ull);
            if (v0) xv0 = x0[k4];
            if (v1) xv1 = x1[k4];
            #pragma unroll
            for (int j = 0; j < LL_; j++) {
                ulonglong2 w = sW2[j * 256 + k4];
                acc0[j] = fma2(xv0.x, w.x, acc0[j]);
                acc0[j] = fma2(xv0.y, w.y, acc0[j]);
                acc1[j] = fma2(xv1.x, w.x, acc1[j]);
                acc1[j] = fma2(xv1.y, w.y, acc1[j]);
            }
        }
        // Butterfly reduce the 18 pair-accumulators across the warp
        #pragma unroll
        for (int j = 0; j < LL_; j++) {
            u64 a = acc0[j];
            u64 b = acc1[j];
            #pragma unroll
            for (int off = 16; off >= 1; off >>= 1) {
                a = add2(a, __shfl_xor_sync(0xffffffffu, a, off));
                b = add2(b, __shfl_xor_sync(0xffffffffu, b, off));
            }
            acc0[j] = a;
            acc1[j] = b;
        }
    }

    // Epilogue: lane 0 -> row0, lane 1 -> row0+1
    float l[LL_];
    if (lane == 0) {
        #pragma unroll
        for (int j = 0; j < LL_; j++) l[j] = pair_sum(acc0[j]);
    } else if (lane == 1) {
        #pragma unroll
        for (int j = 0; j < LL_; j++) l[j] = pair_sum(acc1[j]);
    }
    if (lane < ROWS_PER_WARP) {
        int r = row0 + lane;
        float mx = -3.402823466e+38f;
        #pragma unroll
        for (int j = 0; j < LL_; j++) {
            l[j] += sb[j];
            mx = fmaxf(mx, l[j]);
        }
        float ssum = 0.0f;
        #pragma unroll
        for (int j = 0; j < LL_; j++) {
            l[j] = __expf(l[j] - mx);
            ssum += l[j];
        }
        float inv = __fdividef(1.0f, ssum);
        float* o = out + (size_t)r * LL_;
        #pragma unroll
        for (int j = 0; j < LL_; j++) o[j] = l[j] * inv;
    }
}

// ---------------------------------------------------------------------------
extern "C" void kernel_launch(void* const* d_in, const int* in_sizes, int n_in,
                              void* d_out, int out_size) {
    const float* seq  = (const float*)d_in[0];   // [B,S,H] f32
    const int*   mask = (const int*)d_in[1];     // [B,S]   i32
    const float* W    = (const float*)d_in[2];   // [H,L]   f32
    const float* bias = (const float*)d_in[3];   // [L]     f32
    float* out = (float*)d_out;                  // [B,S,L] f32

    compact_kernel<<<BB_, SS_>>>(mask);

    int grid = (BB_ * SS_) / ROWS_PER_BLOCK;     // 2048
    bertner_main_kernel<<<grid, TPB>>>(seq, W, bias, out);
}

// round 3
// speedup vs baseline: 1.3112x; 1.2917x over previous
#include <cuda_runtime.h>
#include <cuda_bf16.h>

// Problem shape (fixed)
#define BB_ 64
#define SS_ 512
#define HH_ 1024
#define LL_ 9

#define TPB 128
#define ROWS_PER_WARP 4
#define ROWS_PER_BLOCK 16         // 4 warps * 4 rows
#define NCHUNK 16                 // 512 / 32

// Transposed weights [L][H], written once by transpose_W
__device__ float g_Wt[LL_ * HH_];

typedef unsigned long long u64;

__device__ __forceinline__ u64 fma2(u64 a, u64 b, u64 c) {
    u64 d;
    asm("fma.rn.f32x2 %0, %1, %2, %3;" : "=l"(d) : "l"(a), "l"(b), "l"(c));
    return d;
}
__device__ __forceinline__ u64 add2(u64 a, u64 b) {
    u64 d;
    asm("add.rn.f32x2 %0, %1, %2;" : "=l"(d) : "l"(a), "l"(b));
    return d;
}
__device__ __forceinline__ float pair_sum(u64 v) {
    float lo = __uint_as_float((unsigned)(v & 0xffffffffull));
    float hi = __uint_as_float((unsigned)(v >> 32));
    return lo + hi;
}

// ---------------------------------------------------------------------------
// One-shot: W [H,L] -> g_Wt [L,H]  (9 blocks x 1024 threads)
// ---------------------------------------------------------------------------
__global__ void transpose_W(const float* __restrict__ W) {
    int j = blockIdx.x;
    int k = threadIdx.x;
    g_Wt[j * HH_ + k] = W[k * LL_ + j];
}

// ---------------------------------------------------------------------------
// Main kernel: block = 16 rows of one batch. Inline mask scan -> src indices.
// Warp computes 4 rows; half-warps split the 9 outputs (j0..3 / j4..8) so
// each smem W read serves 4 rows with only 20 u64 accumulators per lane.
// ---------------------------------------------------------------------------
__global__ __launch_bounds__(TPB, 4)
void bertner_main_kernel(const float* __restrict__ seq,
                         const int* __restrict__ mask,
                         const float* __restrict__ bias,
                         float* __restrict__ out) {
    __shared__ ulonglong2 sW2[LL_ * 256];    // [j][k4] 36 KB
    __shared__ unsigned mbits[NCHUNK];
    __shared__ int msum[NCHUNK];
    __shared__ int ssrc[ROWS_PER_BLOCK];
    __shared__ int snv;

    int tid  = threadIdx.x;
    int lane = tid & 31;
    int warp = tid >> 5;                      // 0..3

    int b  = blockIdx.x >> 5;                 // 32 blocks per batch
    int d0 = (blockIdx.x & 31) * ROWS_PER_BLOCK;

    // ---- per-block mask scan (512 bits) ----
    #pragma unroll
    for (int r = 0; r < 4; r++) {
        int chunk = warp * 4 + r;             // 0..15
        int s = chunk * 32 + lane;
        int m = (mask[b * SS_ + s] != 0);
        unsigned bal = __ballot_sync(0xffffffffu, m);
        if (lane == 0) mbits[chunk] = bal;
    }
    __syncthreads();
    if (tid < NCHUNK) {
        int v = __popc(mbits[tid]);
        #pragma unroll
        for (int off = 1; off < NCHUNK; off <<= 1) {
            int u = __shfl_up_sync(0x0000ffffu, v, off);
            if (tid >= off) v += u;
        }
        msum[tid] = v;                         // inclusive
        if (tid == NCHUNK - 1) snv = v;
    }
    __syncthreads();
    int nv = snv;
    bool blockHasValid = (d0 < nv);

    // ---- source index for each of this block's 16 rows ----
    if (tid < ROWS_PER_BLOCK) {
        int d = d0 + tid;
        int src = 0;
        if (d < nv) {
            int c = 0, base = 0;
            #pragma unroll
            for (int cc = 0; cc < NCHUNK - 1; cc++)
                if (msum[cc] <= d) { c = cc + 1; base = msum[cc]; }
            unsigned wv = mbits[c];
            int rr = d - base;
            for (int t = 0; t < rr; t++) wv &= wv - 1;  // clear rr lowest set bits
            src = c * 32 + (__ffs(wv) - 1);
        }
        ssrc[tid] = src;
    }

    // ---- stage transposed W (plain conflict-free float4 memcpy) ----
    if (blockHasValid) {
        const float4* s4 = (const float4*)g_Wt;
        float4* dd4 = (float4*)sW2;
        #pragma unroll
        for (int it = 0; it < (LL_ * HH_ / 4) / TPB; it++)   // 18
            dd4[it * TPB + tid] = s4[it * TPB + tid];
    }
    __syncthreads();

    // ---- main GEMV ----
    int jg = lane >> 4;                        // 0: j0..3, 1: j4..8
    int kl = lane & 15;
    int jbase = jg * 4;

    int rw0 = warp * ROWS_PER_WARP;
    bool warpValid = (d0 + rw0) < nv;

    bool vld[ROWS_PER_WARP];
    const ulonglong2* xp[ROWS_PER_WARP];
    #pragma unroll
    for (int p = 0; p < ROWS_PER_WARP; p++) {
        int d = d0 + rw0 + p;
        vld[p] = (d < nv);
        int src = ssrc[rw0 + p];
        xp[p] = (const ulonglong2*)(seq + ((size_t)b * SS_ + (size_t)src) * HH_);
    }

    u64 acc[ROWS_PER_WARP][5];
    #pragma unroll
    for (int p = 0; p < ROWS_PER_WARP; p++)
        #pragma unroll
        for (int jj = 0; jj < 5; jj++) acc[p][jj] = 0ull;

    if (warpValid) {
        #pragma unroll 2
        for (int i = 0; i < 16; i++) {
            int k4 = i * 16 + kl;              // float4 index, dup across jg -> merged
            ulonglong2 xv[ROWS_PER_WARP];
            #pragma unroll
            for (int p = 0; p < ROWS_PER_WARP; p++) {
                xv[p] = make_ulonglong2(0ull, 0ull);
                if (vld[p]) xv[p] = xp[p][k4];
            }
            #pragma unroll
            for (int jj = 0; jj < 5; jj++) {
                if (jj < 4 || jg) {
                    ulonglong2 w = sW2[(jbase + jj) * 256 + k4];
                    #pragma unroll
                    for (int p = 0; p < ROWS_PER_WARP; p++) {
                        acc[p][jj] = fma2(xv[p].x, w.x, acc[p][jj]);
                        acc[p][jj] = fma2(xv[p].y, w.y, acc[p][jj]);
                    }
                }
            }
        }
        // reduce over the 16 k-lanes of each half-warp
        #pragma unroll
        for (int p = 0; p < ROWS_PER_WARP; p++)
            #pragma unroll
            for (int jj = 0; jj < 5; jj++) {
                u64 a = acc[p][jj];
                #pragma unroll
                for (int off = 8; off >= 1; off >>= 1)
                    a = add2(a, __shfl_xor_sync(0xffffffffu, a, off));
                acc[p][jj] = a;
            }
    }

    // ---- epilogue: lane p (jg=0) assembles row p's 9 logits ----
    #pragma unroll
    for (int p = 0; p < ROWS_PER_WARP; p++) {
        float v[5];
        #pragma unroll
        for (int jj = 0; jj < 5; jj++) v[jj] = pair_sum(acc[p][jj]);
        float hi[5];
        #pragma unroll
        for (int jj = 0; jj < 5; jj++)
            hi[jj] = __shfl_xor_sync(0xffffffffu, v[jj], 16);
        if (lane == p) {
            float l[LL_];
            l[0] = v[0]; l[1] = v[1]; l[2] = v[2]; l[3] = v[3];
            l[4] = hi[0]; l[5] = hi[1]; l[6] = hi[2]; l[7] = hi[3]; l[8] = hi[4];
            float mx = -3.402823466e+38f;
            #pragma unroll
            for (int j = 0; j < LL_; j++) {
                l[j] += __ldg(&bias[j]);
                mx = fmaxf(mx, l[j]);
            }
            float ssum = 0.0f;
            #pragma unroll
            for (int j = 0; j < LL_; j++) {
                l[j] = __expf(l[j] - mx);
                ssum += l[j];
            }
            float inv = __fdividef(1.0f, ssum);
            int rglob = b * SS_ + d0 + rw0 + p;
            float* o = out + (size_t)rglob * LL_;
            #pragma unroll
            for (int j = 0; j < LL_; j++) o[j] = l[j] * inv;
        }
    }
}

// ---------------------------------------------------------------------------
extern "C" void kernel_launch(void* const* d_in, const int* in_sizes, int n_in,
                              void* d_out, int out_size) {
    const float* seq  = (const float*)d_in[0];   // [B,S,H] f32
    const int*   mask = (const int*)d_in[1];     // [B,S]   i32
    const float* W    = (const float*)d_in[2];   // [H,L]   f32
    const float* bias = (const float*)d_in[3];   // [L]     f32
    float* out = (float*)d_out;                  // [B,S,L] f32

    transpose_W<<<LL_, HH_>>>(W);

    int grid = (BB_ * SS_) / ROWS_PER_BLOCK;     // 2048
    bertner_main_kernel<<<grid, TPB>>>(seq, mask, bias, out);
}